// round 4
// baseline (speedup 1.0000x reference)
#include <cuda_runtime.h>
#include <cstdint>

static constexpr int Bc = 2;
static constexpr int Sc = 2048;
static constexpr int Ec = 1024;
static constexpr int Hc = 16;
static constexpr int Dc = 64;

// Scratch (__device__ globals per allocation rules)
__device__ float g_q  [(size_t)Bc * Hc * Sc * Dc];   // (b,h,s,d)
__device__ float g_k  [(size_t)Bc * Hc * Sc * Dc];   // (b,h,s,d)
__device__ float g_vT [(size_t)Bc * Hc * Dc * Sc];   // (b,h,d,s)
__device__ float g_ctx[(size_t)Bc * Sc * Ec];        // (b,s,E)

// round-to-nearest tf32 bits
__device__ __forceinline__ uint32_t tf32r(float x) {
    uint32_t u = __float_as_uint(x);
    return (u + 0x1000u) & 0xFFFFE000u;
}
__device__ __forceinline__ float tf32f(float x) { return __uint_as_float(tf32r(x)); }

__device__ __forceinline__ void mma8(float* d, const uint32_t* a, uint32_t b0, uint32_t b1) {
    asm volatile(
        "mma.sync.aligned.m16n8k8.row.col.f32.tf32.tf32.f32 "
        "{%0,%1,%2,%3}, {%4,%5,%6,%7}, {%8,%9}, {%0,%1,%2,%3};"
        : "+f"(d[0]), "+f"(d[1]), "+f"(d[2]), "+f"(d[3])
        : "r"(a[0]), "r"(a[1]), "r"(a[2]), "r"(a[3]), "r"(b0), "r"(b1));
}

// ---------------------------------------------------------------------------
// tf32 mma.sync GEMM for projections: C = A @ B^T * scale (+bias)
// EPI: 0 row-major C | 1 head-split (b,h,s,d) | 2 transposed head-split (b,h,d,s)
// ---------------------------------------------------------------------------
template <int BN, int EPI>
__global__ __launch_bounds__(256)
void mma_gemm(const float* __restrict__ A, const float* __restrict__ Bm,
              const float* __restrict__ bias, float* __restrict__ C,
              int N, int K, long sA, long sB, long sC, float scale)
{
    constexpr int WARPS_M = 2;
    constexpr int WM = 64;
    constexpr int WN = BN / 4;
    constexpr int MT = 4;
    constexpr int NT = WN / 8;
    constexpr int NB8 = BN / 8;
    constexpr int AF = 4096;
    constexpr int BF = BN * 32;
    constexpr int NLB = BN / 32;

    extern __shared__ uint32_t sm[];
    uint32_t* Abuf = sm;
    uint32_t* Bbuf = sm + 2 * AF;

    const int tid  = threadIdx.x;
    const int wid  = tid >> 5;
    const int lane = tid & 31;
    const int wm   = wid % WARPS_M;
    const int wn   = wid / WARPS_M;

    A  += (long)blockIdx.z * sA;
    Bm += (long)blockIdx.z * sB;
    C  += (long)blockIdx.z * sC;
    const int m0 = blockIdx.y * 128;
    const int n0 = blockIdx.x * BN;

    const int lrow  = tid >> 3;
    const int c4    = (tid & 7) * 4;
    const int kt_s  = c4 >> 3;
    const int reghi = (c4 >> 2) & 1;

    const float* Ap = A  + (long)m0 * K;
    const float* Bp = Bm + (long)n0 * K;
    const int nk = K >> 5;

    float4 aR[4], bR[NLB];
    float acc[MT][NT][4];
#pragma unroll
    for (int i = 0; i < MT; i++)
#pragma unroll
        for (int j = 0; j < NT; j++)
#pragma unroll
            for (int r = 0; r < 4; r++) acc[i][j][r] = 0.0f;

    auto ldg = [&](int it) {
        const int k0 = it << 5;
#pragma unroll
        for (int i = 0; i < 4; i++)
            aR[i] = *(const float4*)(Ap + (long)(lrow + i * 32) * K + k0 + c4);
#pragma unroll
        for (int i = 0; i < NLB; i++)
            bR[i] = *(const float4*)(Bp + (long)(lrow + i * 32) * K + k0 + c4);
    };

    auto sts = [&](int s) {
        uint32_t* Asd = Abuf + s * AF;
        uint32_t* Bsd = Bbuf + s * BF;
#pragma unroll
        for (int i = 0; i < 4; i++) {
            const int row = lrow + i * 32;
            const int mt  = row >> 4;
            const int reg = ((row >> 3) & 1) + 2 * reghi;
            const int lb  = (row & 7) * 4;
            const float* v = (const float*)&aR[i];
#pragma unroll
            for (int j = 0; j < 4; j++) {
                const int ln = (lb + j) ^ kt_s;
                Asd[((kt_s * 8 + mt) * 32 + ln) * 4 + reg] = tf32r(v[j]);
            }
        }
#pragma unroll
        for (int i = 0; i < NLB; i++) {
            const int n  = lrow + i * 32;
            const int nt = n >> 3;
            const int lb = (n & 7) * 4;
            const float* v = (const float*)&bR[i];
#pragma unroll
            for (int j = 0; j < 4; j++) {
                const int ln = (lb + j) ^ kt_s;
                Bsd[((kt_s * NB8 + nt) * 32 + ln) * 2 + reghi] = tf32r(v[j]);
            }
        }
    };

    auto compute = [&](int s) {
        const uint32_t* Asd = Abuf + s * AF;
        const uint32_t* Bsd = Bbuf + s * BF;
#pragma unroll
        for (int kt = 0; kt < 4; kt++) {
            const int lx = lane ^ kt;
            uint32_t a[MT][4], b[NT][2];
#pragma unroll
            for (int mt = 0; mt < MT; mt++) {
                uint4 v = *(const uint4*)(Asd + ((kt * 8 + wm * MT + mt) * 32 + lx) * 4);
                a[mt][0] = v.x; a[mt][1] = v.y; a[mt][2] = v.z; a[mt][3] = v.w;
            }
#pragma unroll
            for (int nt = 0; nt < NT; nt++) {
                uint2 v = *(const uint2*)(Bsd + ((kt * NB8 + wn * NT + nt) * 32 + lx) * 2);
                b[nt][0] = v.x; b[nt][1] = v.y;
            }
#pragma unroll
            for (int mt = 0; mt < MT; mt++)
#pragma unroll
                for (int nt = 0; nt < NT; nt++)
                    mma8(acc[mt][nt], a[mt], b[nt][0], b[nt][1]);
        }
    };

    ldg(0);
    sts(0);
    __syncthreads();
    for (int it = 0; it < nk; it++) {
        const int s = it & 1;
        if (it + 1 < nk) ldg(it + 1);
        compute(s);
        if (it + 1 < nk) { sts(1 - s); __syncthreads(); }
    }

    const int g  = lane >> 2;
    const int t2 = (lane & 3) * 2;
#pragma unroll
    for (int mt = 0; mt < MT; mt++) {
#pragma unroll
        for (int nt = 0; nt < NT; nt++) {
            const int row = m0 + wm * WM + mt * 16 + g;
            const int col = n0 + wn * WN + nt * 8 + t2;
            float c0 = acc[mt][nt][0] * scale;
            float c1 = acc[mt][nt][1] * scale;
            float c2 = acc[mt][nt][2] * scale;
            float c3 = acc[mt][nt][3] * scale;
            if (bias) {
                const float b0 = bias[col], b1 = bias[col + 1];
                c0 += b0; c1 += b1; c2 += b0; c3 += b1;
            }
            if (EPI == 0) {
                *(float2*)(C + (long)row * N + col)       = make_float2(c0, c1);
                *(float2*)(C + (long)(row + 8) * N + col) = make_float2(c2, c3);
            } else if (EPI == 1) {
                const int b = row >> 11, si = row & 2047, h = col >> 6, d = col & 63;
                float* p = C + (((long)(b * Hc + h) * Sc + si) * Dc + d);
                *(float2*)p            = make_float2(c0, c1);
                *(float2*)(p + 8 * Dc) = make_float2(c2, c3);
            } else {
                const int b = row >> 11, si = row & 2047, h = col >> 6, d = col & 63;
                float* p = C + (((long)(b * Hc + h) * Dc + d) * Sc + si);
                p[0] = c0;  p[Sc] = c1;
                p[8] = c2;  p[Sc + 8] = c3;
            }
        }
    }
}

// ---------------------------------------------------------------------------
// Fused attention: per CTA = 16 query rows of one (b,h).
//   scores(16x2048) -> SMEM, softmax in SMEM, write attn once, AV from SMEM.
// grid = (Sc/16, B*H), 256 threads.
// ---------------------------------------------------------------------------
static constexpr int SROW = 2052;                 // padded score row stride
static constexpr int KSTG = 128 * 68;             // K stage floats (>= 64*132 V stage)
static constexpr int SMEM_F = (16 * SROW + 2 * KSTG) * 4;

__global__ __launch_bounds__(256)
void attn_fused(const float* __restrict__ q, const float* __restrict__ k,
                const float* __restrict__ vT, float* __restrict__ attn,
                float* __restrict__ ctx)
{
    extern __shared__ float smf[];
    float* S   = smf;                 // 16 x SROW
    float* STG0 = smf + 16 * SROW;    // stage buf 0
    float* STG1 = STG0 + KSTG;        // stage buf 1

    const int tid  = threadIdx.x;
    const int lane = tid & 31;
    const int w    = tid >> 5;
    const int g    = lane >> 2;
    const int t    = lane & 3;

    const int z  = blockIdx.y;                    // b*H + h
    const int m0 = blockIdx.x * 16;

    const float* qb = q  + ((long)z * Sc + m0) * Dc;
    const float* kb = k  + (long)z * Sc * Dc;
    const float* vb = vT + (long)z * Dc * Sc;
    float* attnb    = attn + (long)z * Sc * Sc + (long)m0 * Sc;

    // ---- Q fragments (all warps hold the same 16x64 A tile) ----
    uint32_t aq[8][4];
#pragma unroll
    for (int kc = 0; kc < 8; kc++) {
        const int kk = kc * 8 + t;
        aq[kc][0] = tf32r(qb[(long)g * Dc + kk]);
        aq[kc][1] = tf32r(qb[(long)(g + 8) * Dc + kk]);
        aq[kc][2] = tf32r(qb[(long)g * Dc + kk + 4]);
        aq[kc][3] = tf32r(qb[(long)(g + 8) * Dc + kk + 4]);
    }

    // ---- Phase 1: QK^T into S (scale 0.125) ----
    float4 ld[8];
    const int krow = tid >> 4;            // 0..15 within 16-row slab pattern
    const int kc4  = (tid & 15) * 4;      // 0..60

    auto ldgK = [&](int nc) {
#pragma unroll
        for (int i = 0; i < 8; i++) {
            const int row = i * 16 + krow;
            ld[i] = *(const float4*)(kb + (long)(nc * 128 + row) * Dc + kc4);
        }
    };
    auto stsK = [&](int s) {
        float* d = s ? STG1 : STG0;
#pragma unroll
        for (int i = 0; i < 8; i++) {
            const int row = i * 16 + krow;
            float* p = d + row * 68 + kc4;
            p[0] = tf32f(ld[i].x); p[1] = tf32f(ld[i].y);
            p[2] = tf32f(ld[i].z); p[3] = tf32f(ld[i].w);
        }
    };
    auto compQK = [&](int s, int nc) {
        const float* Kst = s ? STG1 : STG0;
#pragma unroll
        for (int j = 0; j < 2; j++) {
            const int nl = w * 16 + j * 8;
            const float* bp = Kst + (nl + g) * 68;
            float acc[4] = {0.f, 0.f, 0.f, 0.f};
#pragma unroll
            for (int kc = 0; kc < 8; kc++) {
                const uint32_t b0 = __float_as_uint(bp[kc * 8 + t]);
                const uint32_t b1 = __float_as_uint(bp[kc * 8 + t + 4]);
                mma8(acc, aq[kc], b0, b1);
            }
            const int col = nc * 128 + nl + 2 * t;
            S[g * SROW + col]           = acc[0] * 0.125f;
            S[g * SROW + col + 1]       = acc[1] * 0.125f;
            S[(g + 8) * SROW + col]     = acc[2] * 0.125f;
            S[(g + 8) * SROW + col + 1] = acc[3] * 0.125f;
        }
    };

    ldgK(0); stsK(0);
    __syncthreads();
    for (int nc = 0; nc < 16; nc++) {
        const int s = nc & 1;
        if (nc + 1 < 16) ldgK(nc + 1);
        compQK(s, nc);
        if (nc + 1 < 16) { stsK(1 - s); __syncthreads(); }
    }
    __syncthreads();

    // ---- Phase 2: softmax rows (warp w -> rows 2w, 2w+1), write attn once ----
#pragma unroll
    for (int rr = 0; rr < 2; rr++) {
        const int r = w * 2 + rr;
        float* row = S + r * SROW;
        float mx = -1e30f;
#pragma unroll 4
        for (int i = 0; i < 64; i++) mx = fmaxf(mx, row[i * 32 + lane]);
#pragma unroll
        for (int off = 16; off > 0; off >>= 1)
            mx = fmaxf(mx, __shfl_xor_sync(0xFFFFFFFFu, mx, off));
        float sum = 0.f;
#pragma unroll 4
        for (int i = 0; i < 64; i++) {
            const float e = __expf(row[i * 32 + lane] - mx);
            row[i * 32 + lane] = e;
            sum += e;
        }
#pragma unroll
        for (int off = 16; off > 0; off >>= 1)
            sum += __shfl_xor_sync(0xFFFFFFFFu, sum, off);
        const float inv = 1.0f / sum;
        float* arow = attnb + (long)r * Sc;
#pragma unroll 4
        for (int i = 0; i < 64; i++) {
            const float v = row[i * 32 + lane] * inv;
            row[i * 32 + lane] = v;
            arow[i * 32 + lane] = v;
        }
    }
    __syncthreads();

    // ---- Phase 3: ctx = P @ V (warp w -> output cols d in [8w, 8w+8)) ----
    const int vrow = tid >> 5;            // 0..7 slab pattern (64 rows / 8)
    const int vc4  = lane * 4;            // 0..124

    auto ldgV = [&](int sc) {
#pragma unroll
        for (int i = 0; i < 8; i++) {
            const int row = i * 8 + vrow;
            ld[i] = *(const float4*)(vb + (long)row * Sc + sc * 128 + vc4);
        }
    };
    auto stsV = [&](int s) {
        float* d = s ? STG1 : STG0;
#pragma unroll
        for (int i = 0; i < 8; i++) {
            const int row = i * 8 + vrow;
            float* p = d + row * 132 + vc4;
            p[0] = tf32f(ld[i].x); p[1] = tf32f(ld[i].y);
            p[2] = tf32f(ld[i].z); p[3] = tf32f(ld[i].w);
        }
    };

    float accv[4] = {0.f, 0.f, 0.f, 0.f};
    auto compAV = [&](int s, int sc) {
        const float* Vst = s ? STG1 : STG0;
        const float* bp = Vst + (w * 8 + g) * 132;
        const float* s0 = S + g * SROW + sc * 128 + t;
        const float* s1 = S + (g + 8) * SROW + sc * 128 + t;
#pragma unroll
        for (int kc = 0; kc < 16; kc++) {
            uint32_t a[4];
            a[0] = tf32r(s0[kc * 8]);
            a[1] = tf32r(s1[kc * 8]);
            a[2] = tf32r(s0[kc * 8 + 4]);
            a[3] = tf32r(s1[kc * 8 + 4]);
            const uint32_t b0 = __float_as_uint(bp[kc * 8 + t]);
            const uint32_t b1 = __float_as_uint(bp[kc * 8 + t + 4]);
            mma8(accv, a, b0, b1);
        }
    };

    ldgV(0); stsV(0);
    __syncthreads();
    for (int sc = 0; sc < 16; sc++) {
        const int s = sc & 1;
        if (sc + 1 < 16) ldgV(sc + 1);
        compAV(s, sc);
        if (sc + 1 < 16) { stsV(1 - s); __syncthreads(); }
    }

    // ctx store: (b, s, E) with E col = h*64 + w*8 + 2t
    {
        const int b = z >> 4, h = z & 15;
        float* cp = ctx + (long)b * Sc * Ec + (long)(m0 + g) * Ec + h * Dc + w * 8 + 2 * t;
        *(float2*)cp            = make_float2(accv[0], accv[1]);
        *(float2*)(cp + 8 * Ec) = make_float2(accv[2], accv[3]);
    }
}

// ---------------------------------------------------------------------------
extern "C" void kernel_launch(void* const* d_in, const int* in_sizes, int n_in,
                              void* d_out, int out_size)
{
    const float* query = (const float*)d_in[0];
    const float* key   = (const float*)d_in[1];
    const float* value = (const float*)d_in[2];
    const float* Wq    = (const float*)d_in[3];
    const float* bq    = (const float*)d_in[4];
    const float* Wk    = (const float*)d_in[5];
    const float* bk    = (const float*)d_in[6];
    const float* Wv    = (const float*)d_in[7];
    const float* bv    = (const float*)d_in[8];
    const float* Wo    = (const float*)d_in[9];
    const float* bo    = (const float*)d_in[10];

    float* out  = (float*)d_out;
    float* attn = out + (long)Bc * Sc * Ec;

    float *q, *k, *vT, *ctx;
    cudaGetSymbolAddress((void**)&q,   g_q);
    cudaGetSymbolAddress((void**)&k,   g_k);
    cudaGetSymbolAddress((void**)&vT,  g_vT);
    cudaGetSymbolAddress((void**)&ctx, g_ctx);

    constexpr int SMEM128 = (2 * 4096 + 2 * 128 * 32) * 4;  // 65536

    cudaFuncSetAttribute((const void*)mma_gemm<128, 0>, cudaFuncAttributeMaxDynamicSharedMemorySize, SMEM128);
    cudaFuncSetAttribute((const void*)mma_gemm<128, 1>, cudaFuncAttributeMaxDynamicSharedMemorySize, SMEM128);
    cudaFuncSetAttribute((const void*)mma_gemm<128, 2>, cudaFuncAttributeMaxDynamicSharedMemorySize, SMEM128);
    cudaFuncSetAttribute((const void*)attn_fused,       cudaFuncAttributeMaxDynamicSharedMemorySize, SMEM_F);

    const dim3 blk(256);
    const dim3 gp(Ec / 128, (Bc * Sc) / 128, 1);

    // 1) projections
    mma_gemm<128, 1><<<gp, blk, SMEM128>>>(query, Wq, bq, q,  Ec, Ec, 0, 0, 0, 1.0f);
    mma_gemm<128, 1><<<gp, blk, SMEM128>>>(key,   Wk, bk, k,  Ec, Ec, 0, 0, 0, 1.0f);
    mma_gemm<128, 2><<<gp, blk, SMEM128>>>(value, Wv, bv, vT, Ec, Ec, 0, 0, 0, 1.0f);

    // 2) fused QK^T + softmax + attn write + AV -> ctx
    attn_fused<<<dim3(Sc / 16, Bc * Hc), blk, SMEM_F>>>(q, k, vT, attn, ctx);

    // 3) out = ctx @ Wo^T + bo
    mma_gemm<128, 0><<<gp, blk, SMEM128>>>(ctx, Wo, bo, out, Ec, Ec, 0, 0, 0, 1.0f);
}

// round 5
// speedup vs baseline: 1.4317x; 1.4317x over previous
#include <cuda_runtime.h>
#include <cstdint>

static constexpr int Bc = 2;
static constexpr int Sc = 2048;
static constexpr int Ec = 1024;
static constexpr int Hc = 16;
static constexpr int Dc = 64;

// Scratch (__device__ globals per allocation rules)
__device__ float g_q  [(size_t)Bc * Hc * Sc * Dc];   // (b,h,s,d)
__device__ float g_k  [(size_t)Bc * Hc * Sc * Dc];   // (b,h,s,d)
__device__ float g_vT [(size_t)Bc * Hc * Dc * Sc];   // (b,h,d,s)
__device__ float g_ctx[(size_t)Bc * Sc * Ec];        // (b,s,E)

// round-to-nearest tf32 bits
__device__ __forceinline__ uint32_t tf32r(float x) {
    uint32_t u = __float_as_uint(x);
    return (u + 0x1000u) & 0xFFFFE000u;
}

__device__ __forceinline__ void mma8(float* d, const uint32_t* a, uint32_t b0, uint32_t b1) {
    asm volatile(
        "mma.sync.aligned.m16n8k8.row.col.f32.tf32.tf32.f32 "
        "{%0,%1,%2,%3}, {%4,%5,%6,%7}, {%8,%9}, {%0,%1,%2,%3};"
        : "+f"(d[0]), "+f"(d[1]), "+f"(d[2]), "+f"(d[3])
        : "r"(a[0]), "r"(a[1]), "r"(a[2]), "r"(a[3]), "r"(b0), "r"(b1));
}

// ---------------------------------------------------------------------------
// tf32 mma.sync GEMM for projections: C = A @ B^T * scale (+bias)
// EPI: 0 row-major C | 1 head-split (b,h,s,d) | 2 transposed head-split (b,h,d,s)
// (identical to R3's proven kernel)
// ---------------------------------------------------------------------------
template <int BN, int EPI>
__global__ __launch_bounds__(256)
void mma_gemm(const float* __restrict__ A, const float* __restrict__ Bm,
              const float* __restrict__ bias, float* __restrict__ C,
              int N, int K, long sA, long sB, long sC, float scale)
{
    constexpr int WARPS_M = 2;
    constexpr int WM = 64;
    constexpr int WN = BN / 4;
    constexpr int MT = 4;
    constexpr int NT = WN / 8;
    constexpr int NB8 = BN / 8;
    constexpr int AF = 4096;
    constexpr int BF = BN * 32;
    constexpr int NLB = BN / 32;

    extern __shared__ uint32_t sm[];
    uint32_t* Abuf = sm;
    uint32_t* Bbuf = sm + 2 * AF;

    const int tid  = threadIdx.x;
    const int wid  = tid >> 5;
    const int lane = tid & 31;
    const int wm   = wid % WARPS_M;
    const int wn   = wid / WARPS_M;

    A  += (long)blockIdx.z * sA;
    Bm += (long)blockIdx.z * sB;
    C  += (long)blockIdx.z * sC;
    const int m0 = blockIdx.y * 128;
    const int n0 = blockIdx.x * BN;

    const int lrow  = tid >> 3;
    const int c4    = (tid & 7) * 4;
    const int kt_s  = c4 >> 3;
    const int reghi = (c4 >> 2) & 1;

    const float* Ap = A  + (long)m0 * K;
    const float* Bp = Bm + (long)n0 * K;
    const int nk = K >> 5;

    float4 aR[4], bR[NLB];
    float acc[MT][NT][4];
#pragma unroll
    for (int i = 0; i < MT; i++)
#pragma unroll
        for (int j = 0; j < NT; j++)
#pragma unroll
            for (int r = 0; r < 4; r++) acc[i][j][r] = 0.0f;

    auto ldg = [&](int it) {
        const int k0 = it << 5;
#pragma unroll
        for (int i = 0; i < 4; i++)
            aR[i] = *(const float4*)(Ap + (long)(lrow + i * 32) * K + k0 + c4);
#pragma unroll
        for (int i = 0; i < NLB; i++)
            bR[i] = *(const float4*)(Bp + (long)(lrow + i * 32) * K + k0 + c4);
    };

    auto sts = [&](int s) {
        uint32_t* Asd = Abuf + s * AF;
        uint32_t* Bsd = Bbuf + s * BF;
#pragma unroll
        for (int i = 0; i < 4; i++) {
            const int row = lrow + i * 32;
            const int mt  = row >> 4;
            const int reg = ((row >> 3) & 1) + 2 * reghi;
            const int lb  = (row & 7) * 4;
            const float* v = (const float*)&aR[i];
#pragma unroll
            for (int j = 0; j < 4; j++) {
                const int ln = (lb + j) ^ kt_s;
                Asd[((kt_s * 8 + mt) * 32 + ln) * 4 + reg] = tf32r(v[j]);
            }
        }
#pragma unroll
        for (int i = 0; i < NLB; i++) {
            const int n  = lrow + i * 32;
            const int nt = n >> 3;
            const int lb = (n & 7) * 4;
            const float* v = (const float*)&bR[i];
#pragma unroll
            for (int j = 0; j < 4; j++) {
                const int ln = (lb + j) ^ kt_s;
                Bsd[((kt_s * NB8 + nt) * 32 + ln) * 2 + reghi] = tf32r(v[j]);
            }
        }
    };

    auto compute = [&](int s) {
        const uint32_t* Asd = Abuf + s * AF;
        const uint32_t* Bsd = Bbuf + s * BF;
#pragma unroll
        for (int kt = 0; kt < 4; kt++) {
            const int lx = lane ^ kt;
            uint32_t a[MT][4], b[NT][2];
#pragma unroll
            for (int mt = 0; mt < MT; mt++) {
                uint4 v = *(const uint4*)(Asd + ((kt * 8 + wm * MT + mt) * 32 + lx) * 4);
                a[mt][0] = v.x; a[mt][1] = v.y; a[mt][2] = v.z; a[mt][3] = v.w;
            }
#pragma unroll
            for (int nt = 0; nt < NT; nt++) {
                uint2 v = *(const uint2*)(Bsd + ((kt * NB8 + wn * NT + nt) * 32 + lx) * 2);
                b[nt][0] = v.x; b[nt][1] = v.y;
            }
#pragma unroll
            for (int mt = 0; mt < MT; mt++)
#pragma unroll
                for (int nt = 0; nt < NT; nt++)
                    mma8(acc[mt][nt], a[mt], b[nt][0], b[nt][1]);
        }
    };

    ldg(0);
    sts(0);
    __syncthreads();
    for (int it = 0; it < nk; it++) {
        const int s = it & 1;
        if (it + 1 < nk) ldg(it + 1);
        compute(s);
        if (it + 1 < nk) { sts(1 - s); __syncthreads(); }
    }

    const int g  = lane >> 2;
    const int t2 = (lane & 3) * 2;
#pragma unroll
    for (int mt = 0; mt < MT; mt++) {
#pragma unroll
        for (int nt = 0; nt < NT; nt++) {
            const int row = m0 + wm * WM + mt * 16 + g;
            const int col = n0 + wn * WN + nt * 8 + t2;
            float c0 = acc[mt][nt][0] * scale;
            float c1 = acc[mt][nt][1] * scale;
            float c2 = acc[mt][nt][2] * scale;
            float c3 = acc[mt][nt][3] * scale;
            if (bias) {
                const float b0 = bias[col], b1 = bias[col + 1];
                c0 += b0; c1 += b1; c2 += b0; c3 += b1;
            }
            if (EPI == 0) {
                *(float2*)(C + (long)row * N + col)       = make_float2(c0, c1);
                *(float2*)(C + (long)(row + 8) * N + col) = make_float2(c2, c3);
            } else if (EPI == 1) {
                const int b = row >> 11, si = row & 2047, h = col >> 6, d = col & 63;
                float* p = C + (((long)(b * Hc + h) * Sc + si) * Dc + d);
                *(float2*)p            = make_float2(c0, c1);
                *(float2*)(p + 8 * Dc) = make_float2(c2, c3);
            } else {
                const int b = row >> 11, si = row & 2047, h = col >> 6, d = col & 63;
                float* p = C + (((long)(b * Hc + h) * Dc + d) * Sc + si);
                p[0] = c0;  p[Sc] = c1;
                p[8] = c2;  p[Sc + 8] = c3;
            }
        }
    }
}

// ---------------------------------------------------------------------------
// One-pass attention: CTA = 128 query rows x one head, 512 threads (16 warps,
// 4x4 over S 128x128 chunks). Pass 1: S-MMA -> exp -> rowsum(reg) + P smem +
// AV-MMA (unnormalized). Reduce -> inv. Pass 2: recompute S, write normalized
// attn (only attn DRAM traffic). ctx = accv * inv.
// SMEM: Q 32K | K 32K | V 32K | P 64K | RED 2K | INV 0.5K  = 162.5 KB
// ---------------------------------------------------------------------------
static constexpr int ATT_SMEM = (8192 + 8192 + 8192 + 16384 + 512 + 128) * 4;

__global__ __launch_bounds__(512)
void attn_onepass(const float* __restrict__ q, const float* __restrict__ k,
                  const float* __restrict__ vT, float* __restrict__ attn,
                  float* __restrict__ ctx)
{
    extern __shared__ uint32_t sm[];
    uint32_t* Qs = sm;             // 8192: kt(8) x mt(8) x 32 x 4
    uint32_t* Ks = sm + 8192;      // 8192: kt(8) x nt(16) x 32 x 2
    uint32_t* Vs = sm + 16384;     // 8192: kt2(16) x nt(8) x 32 x 2
    uint32_t* Ps = sm + 24576;     // 16384: kt2(16) x mt(8) x 32 x 4
    float* RED = (float*)(sm + 40960);   // 512
    float* INV = (float*)(sm + 41472);   // 128

    const int tid  = threadIdx.x;
    const int wid  = tid >> 5;
    const int lane = tid & 31;
    const int wm   = wid & 3;      // 4 row groups of 32
    const int wn   = wid >> 2;     // 4 col groups
    const int g    = lane >> 2;
    const int t    = lane & 3;

    const int z  = blockIdx.y;
    const int m0 = blockIdx.x * 128;

    const float* qb = q  + ((long)z * Sc + m0) * Dc;
    const float* kb = k  + (long)z * Sc * Dc;
    const float* vb = vT + (long)z * Dc * Sc;
    float* attnb    = attn + (long)z * Sc * Sc + (long)m0 * Sc;

    // ---- load Q once into A-frag layout ----
#pragma unroll
    for (int i = 0; i < 4; i++) {
        const int idx = tid + i * 512;
        const int row = idx >> 4;
        const int c4  = (idx & 15) * 4;
        const int kt = c4 >> 3, reghi = (c4 >> 2) & 1;
        const int mt = row >> 4, reg = ((row >> 3) & 1) + 2 * reghi;
        const int ln0 = (row & 7) * 4;
        float4 v = *(const float4*)(qb + (long)row * Dc + c4);
        const float* pv = (const float*)&v;
#pragma unroll
        for (int j = 0; j < 4; j++) {
            const int ln = (ln0 + j) ^ kt;
            Qs[((kt * 8 + mt) * 32 + ln) * 4 + reg] = tf32r(pv[j]);
        }
    }

    auto ldK = [&](int nc) {
#pragma unroll
        for (int i = 0; i < 4; i++) {
            const int idx = tid + i * 512;
            const int n  = idx >> 4;
            const int c4 = (idx & 15) * 4;
            const int kt = c4 >> 3, reghi = (c4 >> 2) & 1;
            const int nt = n >> 3;
            const int ln0 = (n & 7) * 4;
            float4 v = *(const float4*)(kb + (long)(nc * 128 + n) * Dc + c4);
            const float* pv = (const float*)&v;
#pragma unroll
            for (int j = 0; j < 4; j++) {
                const int ln = (ln0 + j) ^ kt;
                Ks[((kt * 16 + nt) * 32 + ln) * 2 + reghi] = tf32r(pv[j]);
            }
        }
    };

    auto ldV = [&](int nc) {
#pragma unroll
        for (int i = 0; i < 4; i++) {
            const int idx = tid + i * 512;
            const int d  = idx >> 5;
            const int c4 = (idx & 31) * 4;
            const int kt2 = c4 >> 3, s2 = kt2 & 7, reghi = (c4 >> 2) & 1;
            const int nt = d >> 3;
            const int ln0 = (d & 7) * 4;
            float4 v = *(const float4*)(vb + (long)d * Sc + nc * 128 + c4);
            const float* pv = (const float*)&v;
#pragma unroll
            for (int j = 0; j < 4; j++) {
                const int ln = (ln0 + j) ^ s2;
                Vs[((kt2 * 8 + nt) * 32 + ln) * 2 + reghi] = tf32r(pv[j]);
            }
        }
    };

    auto smma = [&](float accs[2][4][4]) {
#pragma unroll
        for (int a0 = 0; a0 < 2; a0++)
#pragma unroll
            for (int a1 = 0; a1 < 4; a1++)
#pragma unroll
                for (int a2 = 0; a2 < 4; a2++) accs[a0][a1][a2] = 0.0f;
#pragma unroll
        for (int kt = 0; kt < 8; kt++) {
            const int lx = lane ^ kt;
            uint32_t a[2][4], b[4][2];
#pragma unroll
            for (int mtl = 0; mtl < 2; mtl++) {
                uint4 v = *(const uint4*)(Qs + ((kt * 8 + wm * 2 + mtl) * 32 + lx) * 4);
                a[mtl][0] = v.x; a[mtl][1] = v.y; a[mtl][2] = v.z; a[mtl][3] = v.w;
            }
#pragma unroll
            for (int ntl = 0; ntl < 4; ntl++) {
                uint2 v = *(const uint2*)(Ks + ((kt * 16 + wn * 4 + ntl) * 32 + lx) * 2);
                b[ntl][0] = v.x; b[ntl][1] = v.y;
            }
#pragma unroll
            for (int mtl = 0; mtl < 2; mtl++)
#pragma unroll
                for (int ntl = 0; ntl < 4; ntl++)
                    mma8(accs[mtl][ntl], a[mtl], b[ntl][0], b[ntl][1]);
        }
    };

    auto stP = [&](int r, int c, float p) {
        const int kt2 = c >> 3, s2 = kt2 & 7;
        const int reg = ((r >> 3) & 1) + 2 * ((c >> 2) & 1);
        const int mt = r >> 4;
        const int ln = (((r & 7) * 4) + (c & 3)) ^ s2;
        Ps[((kt2 * 8 + mt) * 32 + ln) * 4 + reg] = tf32r(p);
    };

    float accv[2][2][4];
#pragma unroll
    for (int a0 = 0; a0 < 2; a0++)
#pragma unroll
        for (int a1 = 0; a1 < 2; a1++)
#pragma unroll
            for (int a2 = 0; a2 < 4; a2++) accv[a0][a1][a2] = 0.0f;
    float rs[2][2] = {{0.f, 0.f}, {0.f, 0.f}};

    // ================= pass 1 =================
#pragma unroll 1
    for (int nc = 0; nc < 16; nc++) {
        __syncthreads();                 // prior S-MMA/AV reads of K,V,P done
        ldK(nc);
        ldV(nc);
        __syncthreads();

        float accs[2][4][4];
        smma(accs);

#pragma unroll
        for (int mtl = 0; mtl < 2; mtl++) {
            const int r0 = wm * 32 + mtl * 16 + g;
#pragma unroll
            for (int ntl = 0; ntl < 4; ntl++) {
                const int c = wn * 32 + ntl * 8 + 2 * t;
                const float p0 = __expf(accs[mtl][ntl][0] * 0.125f);
                const float p1 = __expf(accs[mtl][ntl][1] * 0.125f);
                const float p2 = __expf(accs[mtl][ntl][2] * 0.125f);
                const float p3 = __expf(accs[mtl][ntl][3] * 0.125f);
                rs[mtl][0] += p0 + p1;
                rs[mtl][1] += p2 + p3;
                stP(r0,     c,     p0);
                stP(r0,     c + 1, p1);
                stP(r0 + 8, c,     p2);
                stP(r0 + 8, c + 1, p3);
            }
        }
        __syncthreads();

        // AV-MMA on this chunk (unnormalized P)
#pragma unroll
        for (int kt2 = 0; kt2 < 16; kt2++) {
            const int lx = lane ^ (kt2 & 7);
            uint32_t a[2][4], b[2][2];
#pragma unroll
            for (int mtl = 0; mtl < 2; mtl++) {
                uint4 v = *(const uint4*)(Ps + ((kt2 * 8 + wm * 2 + mtl) * 32 + lx) * 4);
                a[mtl][0] = v.x; a[mtl][1] = v.y; a[mtl][2] = v.z; a[mtl][3] = v.w;
            }
#pragma unroll
            for (int ntl = 0; ntl < 2; ntl++) {
                uint2 v = *(const uint2*)(Vs + ((kt2 * 8 + wn * 2 + ntl) * 32 + lx) * 2);
                b[ntl][0] = v.x; b[ntl][1] = v.y;
            }
#pragma unroll
            for (int mtl = 0; mtl < 2; mtl++)
#pragma unroll
                for (int ntl = 0; ntl < 2; ntl++)
                    mma8(accv[mtl][ntl], a[mtl], b[ntl][0], b[ntl][1]);
        }
    }

    // ---- rowsum reduce -> INV ----
#pragma unroll
    for (int mtl = 0; mtl < 2; mtl++)
#pragma unroll
        for (int rr = 0; rr < 2; rr++) {
            float v = rs[mtl][rr];
            v += __shfl_xor_sync(0xFFFFFFFFu, v, 1);
            v += __shfl_xor_sync(0xFFFFFFFFu, v, 2);
            if (t == 0) RED[wn * 128 + wm * 32 + mtl * 16 + rr * 8 + g] = v;
        }
    __syncthreads();
    if (tid < 128)
        INV[tid] = 1.0f / (RED[tid] + RED[128 + tid] + RED[256 + tid] + RED[384 + tid]);
    __syncthreads();

    // ================= pass 2: recompute S, write normalized attn =========
#pragma unroll 1
    for (int nc = 0; nc < 16; nc++) {
        __syncthreads();
        ldK(nc);
        __syncthreads();

        float accs[2][4][4];
        smma(accs);

#pragma unroll
        for (int mtl = 0; mtl < 2; mtl++) {
            const int r0 = wm * 32 + mtl * 16 + g;
            const float i0 = INV[r0], i1 = INV[r0 + 8];
#pragma unroll
            for (int ntl = 0; ntl < 4; ntl++) {
                const int c = nc * 128 + wn * 32 + ntl * 8 + 2 * t;
                const float p0 = __expf(accs[mtl][ntl][0] * 0.125f) * i0;
                const float p1 = __expf(accs[mtl][ntl][1] * 0.125f) * i0;
                const float p2 = __expf(accs[mtl][ntl][2] * 0.125f) * i1;
                const float p3 = __expf(accs[mtl][ntl][3] * 0.125f) * i1;
                *(float2*)(attnb + (long)r0 * Sc + c)       = make_float2(p0, p1);
                *(float2*)(attnb + (long)(r0 + 8) * Sc + c) = make_float2(p2, p3);
            }
        }
    }

    // ---- ctx = accv * inv -> merged (b,s,E) ----
    {
        const int b = z >> 4, h = z & 15;
#pragma unroll
        for (int mtl = 0; mtl < 2; mtl++) {
            const int r0 = wm * 32 + mtl * 16 + g;
            const float i0 = INV[r0], i1 = INV[r0 + 8];
#pragma unroll
            for (int ntl = 0; ntl < 2; ntl++) {
                const int d = wn * 16 + ntl * 8 + 2 * t;
                float* p = ctx + (long)b * Sc * Ec + (long)(m0 + r0) * Ec + h * Dc + d;
                *(float2*)p = make_float2(accv[mtl][ntl][0] * i0, accv[mtl][ntl][1] * i0);
                *(float2*)(p + 8 * Ec) = make_float2(accv[mtl][ntl][2] * i1, accv[mtl][ntl][3] * i1);
            }
        }
    }
}

// ---------------------------------------------------------------------------
extern "C" void kernel_launch(void* const* d_in, const int* in_sizes, int n_in,
                              void* d_out, int out_size)
{
    const float* query = (const float*)d_in[0];
    const float* key   = (const float*)d_in[1];
    const float* value = (const float*)d_in[2];
    const float* Wq    = (const float*)d_in[3];
    const float* bq    = (const float*)d_in[4];
    const float* Wk    = (const float*)d_in[5];
    const float* bk    = (const float*)d_in[6];
    const float* Wv    = (const float*)d_in[7];
    const float* bv    = (const float*)d_in[8];
    const float* Wo    = (const float*)d_in[9];
    const float* bo    = (const float*)d_in[10];

    float* out  = (float*)d_out;
    float* attn = out + (long)Bc * Sc * Ec;

    float *q, *k, *vT, *ctx;
    cudaGetSymbolAddress((void**)&q,   g_q);
    cudaGetSymbolAddress((void**)&k,   g_k);
    cudaGetSymbolAddress((void**)&vT,  g_vT);
    cudaGetSymbolAddress((void**)&ctx, g_ctx);

    constexpr int SMEM128 = (2 * 4096 + 2 * 128 * 32) * 4;  // 65536

    cudaFuncSetAttribute((const void*)mma_gemm<128, 0>, cudaFuncAttributeMaxDynamicSharedMemorySize, SMEM128);
    cudaFuncSetAttribute((const void*)mma_gemm<128, 1>, cudaFuncAttributeMaxDynamicSharedMemorySize, SMEM128);
    cudaFuncSetAttribute((const void*)mma_gemm<128, 2>, cudaFuncAttributeMaxDynamicSharedMemorySize, SMEM128);
    cudaFuncSetAttribute((const void*)attn_onepass,     cudaFuncAttributeMaxDynamicSharedMemorySize, ATT_SMEM);

    const dim3 blk(256);
    const dim3 gp(Ec / 128, (Bc * Sc) / 128, 1);

    // 1) projections
    mma_gemm<128, 1><<<gp, blk, SMEM128>>>(query, Wq, bq, q,  Ec, Ec, 0, 0, 0, 1.0f);
    mma_gemm<128, 1><<<gp, blk, SMEM128>>>(key,   Wk, bk, k,  Ec, Ec, 0, 0, 0, 1.0f);
    mma_gemm<128, 2><<<gp, blk, SMEM128>>>(value, Wv, bv, vT, Ec, Ec, 0, 0, 0, 1.0f);

    // 2) one-pass attention: QK^T + softmax + single attn write + AV
    attn_onepass<<<dim3(Sc / 128, Bc * Hc), 512, ATT_SMEM>>>(q, k, vT, attn, ctx);

    // 3) out = ctx @ Wo^T + bo
    mma_gemm<128, 0><<<gp, blk, SMEM128>>>(ctx, Wo, bo, out, Ec, Ec, 0, 0, 0, 1.0f);
}

// round 6
// speedup vs baseline: 1.6231x; 1.1337x over previous
#include <cuda_runtime.h>
#include <cstdint>

static constexpr int Bc = 2;
static constexpr int Sc = 2048;
static constexpr int Ec = 1024;
static constexpr int Hc = 16;
static constexpr int Dc = 64;

// Scratch (__device__ globals per allocation rules)
__device__ float g_q  [(size_t)Bc * Hc * Sc * Dc];   // (b,h,s,d)
__device__ float g_k  [(size_t)Bc * Hc * Sc * Dc];   // (b,h,s,d)
__device__ float g_vT [(size_t)Bc * Hc * Dc * Sc];   // (b,h,d,s)
__device__ float g_ctx[(size_t)Bc * Sc * Ec];        // (b,s,E)

__device__ __forceinline__ uint32_t tf32r(float x) {
    uint32_t u = __float_as_uint(x);
    return (u + 0x1000u) & 0xFFFFE000u;
}

__device__ __forceinline__ void mma8(float* d, const uint32_t* a, uint32_t b0, uint32_t b1) {
    asm volatile(
        "mma.sync.aligned.m16n8k8.row.col.f32.tf32.tf32.f32 "
        "{%0,%1,%2,%3}, {%4,%5,%6,%7}, {%8,%9}, {%0,%1,%2,%3};"
        : "+f"(d[0]), "+f"(d[1]), "+f"(d[2]), "+f"(d[3])
        : "r"(a[0]), "r"(a[1]), "r"(a[2]), "r"(a[3]), "r"(b0), "r"(b1));
}

// ---------------------------------------------------------------------------
// GEMM core macro-body shared by out-proj (template) and fused QKV kernel.
// C = A @ W^T * scale + bias ; BM=128, BN=128, BK=32, 256 thr, double-buffered.
// ---------------------------------------------------------------------------
template <int BN, int EPI>
__global__ __launch_bounds__(256)
void mma_gemm(const float* __restrict__ A, const float* __restrict__ Bm,
              const float* __restrict__ bias, float* __restrict__ C,
              int N, int K, long sA, long sB, long sC, float scale)
{
    constexpr int WARPS_M = 2;
    constexpr int WM = 64;
    constexpr int WN = BN / 4;
    constexpr int MT = 4;
    constexpr int NT = WN / 8;
    constexpr int NB8 = BN / 8;
    constexpr int AF = 4096;
    constexpr int BF = BN * 32;
    constexpr int NLB = BN / 32;

    extern __shared__ uint32_t sm[];
    uint32_t* Abuf = sm;
    uint32_t* Bbuf = sm + 2 * AF;

    const int tid  = threadIdx.x;
    const int wid  = tid >> 5;
    const int lane = tid & 31;
    const int wm   = wid % WARPS_M;
    const int wn   = wid / WARPS_M;

    A  += (long)blockIdx.z * sA;
    Bm += (long)blockIdx.z * sB;
    C  += (long)blockIdx.z * sC;
    const int m0 = blockIdx.y * 128;
    const int n0 = blockIdx.x * BN;

    const int lrow  = tid >> 3;
    const int c4    = (tid & 7) * 4;
    const int kt_s  = c4 >> 3;
    const int reghi = (c4 >> 2) & 1;

    const float* Ap = A  + (long)m0 * K;
    const float* Bp = Bm + (long)n0 * K;
    const int nk = K >> 5;

    float4 aR[4], bR[NLB];
    float acc[MT][NT][4];
#pragma unroll
    for (int i = 0; i < MT; i++)
#pragma unroll
        for (int j = 0; j < NT; j++)
#pragma unroll
            for (int r = 0; r < 4; r++) acc[i][j][r] = 0.0f;

    auto ldg = [&](int it) {
        const int k0 = it << 5;
#pragma unroll
        for (int i = 0; i < 4; i++)
            aR[i] = *(const float4*)(Ap + (long)(lrow + i * 32) * K + k0 + c4);
#pragma unroll
        for (int i = 0; i < NLB; i++)
            bR[i] = *(const float4*)(Bp + (long)(lrow + i * 32) * K + k0 + c4);
    };

    auto sts = [&](int s) {
        uint32_t* Asd = Abuf + s * AF;
        uint32_t* Bsd = Bbuf + s * BF;
#pragma unroll
        for (int i = 0; i < 4; i++) {
            const int row = lrow + i * 32;
            const int mt  = row >> 4;
            const int reg = ((row >> 3) & 1) + 2 * reghi;
            const int lb  = (row & 7) * 4;
            const float* v = (const float*)&aR[i];
#pragma unroll
            for (int j = 0; j < 4; j++) {
                const int ln = (lb + j) ^ kt_s;
                Asd[((kt_s * 8 + mt) * 32 + ln) * 4 + reg] = tf32r(v[j]);
            }
        }
#pragma unroll
        for (int i = 0; i < NLB; i++) {
            const int n  = lrow + i * 32;
            const int nt = n >> 3;
            const int lb = (n & 7) * 4;
            const float* v = (const float*)&bR[i];
#pragma unroll
            for (int j = 0; j < 4; j++) {
                const int ln = (lb + j) ^ kt_s;
                Bsd[((kt_s * NB8 + nt) * 32 + ln) * 2 + reghi] = tf32r(v[j]);
            }
        }
    };

    auto compute = [&](int s) {
        const uint32_t* Asd = Abuf + s * AF;
        const uint32_t* Bsd = Bbuf + s * BF;
#pragma unroll
        for (int kt = 0; kt < 4; kt++) {
            const int lx = lane ^ kt;
            uint32_t a[MT][4], b[NT][2];
#pragma unroll
            for (int mt = 0; mt < MT; mt++) {
                uint4 v = *(const uint4*)(Asd + ((kt * 8 + wm * MT + mt) * 32 + lx) * 4);
                a[mt][0] = v.x; a[mt][1] = v.y; a[mt][2] = v.z; a[mt][3] = v.w;
            }
#pragma unroll
            for (int nt = 0; nt < NT; nt++) {
                uint2 v = *(const uint2*)(Bsd + ((kt * NB8 + wn * NT + nt) * 32 + lx) * 2);
                b[nt][0] = v.x; b[nt][1] = v.y;
            }
#pragma unroll
            for (int mt = 0; mt < MT; mt++)
#pragma unroll
                for (int nt = 0; nt < NT; nt++)
                    mma8(acc[mt][nt], a[mt], b[nt][0], b[nt][1]);
        }
    };

    ldg(0);
    sts(0);
    __syncthreads();
    for (int it = 0; it < nk; it++) {
        const int s = it & 1;
        if (it + 1 < nk) ldg(it + 1);
        compute(s);
        if (it + 1 < nk) { sts(1 - s); __syncthreads(); }
    }

    const int g  = lane >> 2;
    const int t2 = (lane & 3) * 2;
#pragma unroll
    for (int mt = 0; mt < MT; mt++) {
#pragma unroll
        for (int nt = 0; nt < NT; nt++) {
            const int row = m0 + wm * WM + mt * 16 + g;
            const int col = n0 + wn * WN + nt * 8 + t2;
            float c0 = acc[mt][nt][0] * scale;
            float c1 = acc[mt][nt][1] * scale;
            float c2 = acc[mt][nt][2] * scale;
            float c3 = acc[mt][nt][3] * scale;
            if (bias) {
                const float b0 = bias[col], b1 = bias[col + 1];
                c0 += b0; c1 += b1; c2 += b0; c3 += b1;
            }
            if (EPI == 0) {
                *(float2*)(C + (long)row * N + col)       = make_float2(c0, c1);
                *(float2*)(C + (long)(row + 8) * N + col) = make_float2(c2, c3);
            } else if (EPI == 1) {
                const int b = row >> 11, si = row & 2047, h = col >> 6, d = col & 63;
                float* p = C + (((long)(b * Hc + h) * Sc + si) * Dc + d);
                *(float2*)p            = make_float2(c0, c1);
                *(float2*)(p + 8 * Dc) = make_float2(c2, c3);
            } else {
                const int b = row >> 11, si = row & 2047, h = col >> 6, d = col & 63;
                float* p = C + (((long)(b * Hc + h) * Dc + d) * Sc + si);
                p[0] = c0;  p[Sc] = c1;
                p[8] = c2;  p[Sc + 8] = c3;
            }
        }
    }
}

// ---------------------------------------------------------------------------
// Fused QKV projection: one launch, blockIdx.z selects {Q,K,V}.
// Q,K -> head-split (b,h,s,d); V -> transposed head-split (b,h,d,s).
// ---------------------------------------------------------------------------
__global__ __launch_bounds__(256)
void qkv_gemm(const float* __restrict__ in0, const float* __restrict__ in1,
              const float* __restrict__ in2,
              const float* __restrict__ W0, const float* __restrict__ W1,
              const float* __restrict__ W2,
              const float* __restrict__ bi0, const float* __restrict__ bi1,
              const float* __restrict__ bi2,
              float* __restrict__ d0, float* __restrict__ d1, float* __restrict__ d2)
{
    constexpr int K = 1024;
    const float* A; const float* Bm; const float* bias; float* C;
    if (blockIdx.z == 0)      { A = in0; Bm = W0; bias = bi0; C = d0; }
    else if (blockIdx.z == 1) { A = in1; Bm = W1; bias = bi1; C = d1; }
    else                      { A = in2; Bm = W2; bias = bi2; C = d2; }

    extern __shared__ uint32_t sm[];
    uint32_t* Abuf = sm;
    uint32_t* Bbuf = sm + 2 * 4096;

    const int tid  = threadIdx.x;
    const int wid  = tid >> 5;
    const int lane = tid & 31;
    const int wm   = wid & 1;
    const int wn   = wid >> 1;

    const int m0 = blockIdx.y * 128;
    const int n0 = blockIdx.x * 128;

    const int lrow  = tid >> 3;
    const int c4    = (tid & 7) * 4;
    const int kt_s  = c4 >> 3;
    const int reghi = (c4 >> 2) & 1;

    const float* Ap = A  + (long)m0 * K;
    const float* Bp = Bm + (long)n0 * K;

    float4 aR[4], bR[4];
    float acc[4][4][4];
#pragma unroll
    for (int i = 0; i < 4; i++)
#pragma unroll
        for (int j = 0; j < 4; j++)
#pragma unroll
            for (int r = 0; r < 4; r++) acc[i][j][r] = 0.0f;

    auto ldg = [&](int it) {
        const int k0 = it << 5;
#pragma unroll
        for (int i = 0; i < 4; i++) {
            aR[i] = *(const float4*)(Ap + (long)(lrow + i * 32) * K + k0 + c4);
            bR[i] = *(const float4*)(Bp + (long)(lrow + i * 32) * K + k0 + c4);
        }
    };

    auto sts = [&](int s) {
        uint32_t* Asd = Abuf + s * 4096;
        uint32_t* Bsd = Bbuf + s * 4096;
#pragma unroll
        for (int i = 0; i < 4; i++) {
            const int row = lrow + i * 32;
            const int mt  = row >> 4;
            const int reg = ((row >> 3) & 1) + 2 * reghi;
            const int lb  = (row & 7) * 4;
            const float* va = (const float*)&aR[i];
            const float* vb = (const float*)&bR[i];
            const int nt = row >> 3;
#pragma unroll
            for (int j = 0; j < 4; j++) {
                const int ln = (lb + j) ^ kt_s;
                Asd[((kt_s * 8 + mt) * 32 + ln) * 4 + reg]  = tf32r(va[j]);
                Bsd[((kt_s * 16 + nt) * 32 + ln) * 2 + reghi] = tf32r(vb[j]);
            }
        }
    };

    auto compute = [&](int s) {
        const uint32_t* Asd = Abuf + s * 4096;
        const uint32_t* Bsd = Bbuf + s * 4096;
#pragma unroll
        for (int kt = 0; kt < 4; kt++) {
            const int lx = lane ^ kt;
            uint32_t a[4][4], b[4][2];
#pragma unroll
            for (int mt = 0; mt < 4; mt++) {
                uint4 v = *(const uint4*)(Asd + ((kt * 8 + wm * 4 + mt) * 32 + lx) * 4);
                a[mt][0] = v.x; a[mt][1] = v.y; a[mt][2] = v.z; a[mt][3] = v.w;
            }
#pragma unroll
            for (int nt = 0; nt < 4; nt++) {
                uint2 v = *(const uint2*)(Bsd + ((kt * 16 + wn * 4 + nt) * 32 + lx) * 2);
                b[nt][0] = v.x; b[nt][1] = v.y;
            }
#pragma unroll
            for (int mt = 0; mt < 4; mt++)
#pragma unroll
                for (int nt = 0; nt < 4; nt++)
                    mma8(acc[mt][nt], a[mt], b[nt][0], b[nt][1]);
        }
    };

    ldg(0);
    sts(0);
    __syncthreads();
    for (int it = 0; it < 32; it++) {
        const int s = it & 1;
        if (it + 1 < 32) ldg(it + 1);
        compute(s);
        if (it + 1 < 32) { sts(1 - s); __syncthreads(); }
    }

    const int g  = lane >> 2;
    const int t2 = (lane & 3) * 2;
    const bool transp = (blockIdx.z == 2);
#pragma unroll
    for (int mt = 0; mt < 4; mt++) {
#pragma unroll
        for (int nt = 0; nt < 4; nt++) {
            const int row = m0 + wm * 64 + mt * 16 + g;
            const int col = n0 + wn * 32 + nt * 8 + t2;
            const float b0 = bias[col], b1 = bias[col + 1];
            const float c0 = acc[mt][nt][0] + b0;
            const float c1 = acc[mt][nt][1] + b1;
            const float c2 = acc[mt][nt][2] + b0;
            const float c3 = acc[mt][nt][3] + b1;
            const int b = row >> 11, si = row & 2047, h = col >> 6, d = col & 63;
            if (!transp) {
                float* p = C + (((long)(b * Hc + h) * Sc + si) * Dc + d);
                *(float2*)p            = make_float2(c0, c1);
                *(float2*)(p + 8 * Dc) = make_float2(c2, c3);
            } else {
                float* p = C + (((long)(b * Hc + h) * Dc + d) * Sc + si);
                p[0] = c0;  p[Sc] = c1;
                p[8] = c2;  p[Sc + 8] = c3;
            }
        }
    }
}

// ---------------------------------------------------------------------------
// attn2: CTA = 128 q-rows x one head, 256 thr. Warp = 16 FULL rows.
// Pass 1: S-MMA -> exp -> reg rowsums + shuffle C->A frags -> AV-MMA (unnorm).
// Pass 2: recompute S, write normalized attn (only attn DRAM touch).
// SMEM: Q frags 32K (resident) + K 32K + V 32K = 96 KB.
// ---------------------------------------------------------------------------
static constexpr int ATT2_SMEM = 3 * 8192 * 4;

__global__ __launch_bounds__(256)
void attn2(const float* __restrict__ q, const float* __restrict__ k,
           const float* __restrict__ vT, float* __restrict__ attn,
           float* __restrict__ ctx)
{
    extern __shared__ uint32_t sm[];
    uint32_t* Qs = sm;            // 8192
    uint32_t* Ks = sm + 8192;     // 8192
    uint32_t* Vs = sm + 16384;    // 8192

    const int tid  = threadIdx.x;
    const int lane = tid & 31;
    const int wid  = tid >> 5;
    const int g    = lane >> 2;
    const int t    = lane & 3;
    const int z    = blockIdx.y;
    const int m0   = blockIdx.x * 128;

    const float* qb = q  + ((long)z * Sc + m0) * Dc;
    const float* kb = k  + (long)z * Sc * Dc;
    const float* vb = vT + (long)z * Dc * Sc;
    float* attnb    = attn + (long)z * Sc * Sc + (long)m0 * Sc;

    // ---- Q -> frag smem once, then to regs ----
#pragma unroll
    for (int i = 0; i < 8; i++) {
        const int idx = tid + i * 256;
        const int row = idx >> 4;
        const int c4  = (idx & 15) * 4;
        const int kt = c4 >> 3, reghi = (c4 >> 2) & 1;
        const int mt = row >> 4, reg = ((row >> 3) & 1) + 2 * reghi;
        const int ln0 = (row & 7) * 4;
        float4 v = *(const float4*)(qb + (long)row * Dc + c4);
        const float* pv = (const float*)&v;
#pragma unroll
        for (int j = 0; j < 4; j++) {
            const int ln = (ln0 + j) ^ kt;
            Qs[((kt * 8 + mt) * 32 + ln) * 4 + reg] = tf32r(pv[j]);
        }
    }
    __syncthreads();
    uint32_t aq[8][4];
#pragma unroll
    for (int kt = 0; kt < 8; kt++) {
        uint4 v = *(const uint4*)(Qs + ((kt * 8 + wid) * 32 + (lane ^ kt)) * 4);
        aq[kt][0] = v.x; aq[kt][1] = v.y; aq[kt][2] = v.z; aq[kt][3] = v.w;
    }

    auto ldK = [&](int nc) {
#pragma unroll
        for (int i = 0; i < 8; i++) {
            const int idx = tid + i * 256;
            const int n  = idx >> 4;
            const int c4 = (idx & 15) * 4;
            const int kt = c4 >> 3, reghi = (c4 >> 2) & 1;
            const int nt = n >> 3;
            const int ln0 = (n & 7) * 4;
            float4 v = *(const float4*)(kb + (long)(nc * 128 + n) * Dc + c4);
            const float* pv = (const float*)&v;
#pragma unroll
            for (int j = 0; j < 4; j++) {
                const int ln = (ln0 + j) ^ kt;
                Ks[((kt * 16 + nt) * 32 + ln) * 2 + reghi] = tf32r(pv[j]);
            }
        }
    };
    auto ldV = [&](int nc) {
#pragma unroll
        for (int i = 0; i < 8; i++) {
            const int idx = tid + i * 256;
            const int d  = idx >> 5;
            const int c4 = (idx & 31) * 4;
            const int kt2 = c4 >> 3, s2 = kt2 & 7, reghi = (c4 >> 2) & 1;
            const int nt = d >> 3;
            const int ln0 = (d & 7) * 4;
            float4 v = *(const float4*)(vb + (long)d * Sc + nc * 128 + c4);
            const float* pv = (const float*)&v;
#pragma unroll
            for (int j = 0; j < 4; j++) {
                const int ln = (ln0 + j) ^ s2;
                Vs[((kt2 * 8 + nt) * 32 + ln) * 2 + reghi] = tf32r(pv[j]);
            }
        }
    };

    float ctxacc[8][4];
#pragma unroll
    for (int i = 0; i < 8; i++)
#pragma unroll
        for (int r = 0; r < 4; r++) ctxacc[i][r] = 0.0f;
    float rs0 = 0.0f, rs1 = 0.0f;

    const int lsrc0 = (lane & ~3) | (t >> 1);
    const int lsrc1 = lsrc0 + 2;
    const bool odd  = (t & 1);

    // ================= pass 1 =================
#pragma unroll 1
    for (int nc = 0; nc < 16; nc++) {
        __syncthreads();
        ldK(nc);
        ldV(nc);
        __syncthreads();

        float c[16][4];
#pragma unroll
        for (int nt = 0; nt < 16; nt++) { c[nt][0] = c[nt][1] = c[nt][2] = c[nt][3] = 0.0f; }
#pragma unroll
        for (int kt = 0; kt < 8; kt++) {
            const int lx = lane ^ kt;
#pragma unroll
            for (int nt = 0; nt < 16; nt++) {
                uint2 b = *(const uint2*)(Ks + ((kt * 16 + nt) * 32 + lx) * 2);
                mma8(c[nt], aq[kt], b.x, b.y);
            }
        }
#pragma unroll
        for (int nt = 0; nt < 16; nt++) {
            c[nt][0] = __expf(c[nt][0] * 0.125f);
            c[nt][1] = __expf(c[nt][1] * 0.125f);
            c[nt][2] = __expf(c[nt][2] * 0.125f);
            c[nt][3] = __expf(c[nt][3] * 0.125f);
            rs0 += c[nt][0] + c[nt][1];
            rs1 += c[nt][2] + c[nt][3];
        }
        // AV: shuffle C-frags into A-frags, MMA against V
#pragma unroll
        for (int kt2 = 0; kt2 < 16; kt2++) {
            const float x0 = __shfl_sync(0xFFFFFFFFu, c[kt2][0], lsrc0);
            const float x1 = __shfl_sync(0xFFFFFFFFu, c[kt2][1], lsrc0);
            const float y0 = __shfl_sync(0xFFFFFFFFu, c[kt2][2], lsrc0);
            const float y1 = __shfl_sync(0xFFFFFFFFu, c[kt2][3], lsrc0);
            const float u0 = __shfl_sync(0xFFFFFFFFu, c[kt2][0], lsrc1);
            const float u1 = __shfl_sync(0xFFFFFFFFu, c[kt2][1], lsrc1);
            const float w0 = __shfl_sync(0xFFFFFFFFu, c[kt2][2], lsrc1);
            const float w1 = __shfl_sync(0xFFFFFFFFu, c[kt2][3], lsrc1);
            uint32_t pa[4];
            pa[0] = tf32r(odd ? x1 : x0);
            pa[1] = tf32r(odd ? y1 : y0);
            pa[2] = tf32r(odd ? u1 : u0);
            pa[3] = tf32r(odd ? w1 : w0);
            const int lx2 = lane ^ (kt2 & 7);
#pragma unroll
            for (int ntv = 0; ntv < 8; ntv++) {
                uint2 b = *(const uint2*)(Vs + ((kt2 * 8 + ntv) * 32 + lx2) * 2);
                mma8(ctxacc[ntv], pa, b.x, b.y);
            }
        }
    }

    // row inverses (rows are warp-exclusive; reduce within quad)
    rs0 += __shfl_xor_sync(0xFFFFFFFFu, rs0, 1);
    rs0 += __shfl_xor_sync(0xFFFFFFFFu, rs0, 2);
    rs1 += __shfl_xor_sync(0xFFFFFFFFu, rs1, 1);
    rs1 += __shfl_xor_sync(0xFFFFFFFFu, rs1, 2);
    const float inv0 = 1.0f / rs0;
    const float inv1 = 1.0f / rs1;
    const int r0 = wid * 16;

    // ================= pass 2: recompute S, write normalized attn ==========
#pragma unroll 1
    for (int nc = 0; nc < 16; nc++) {
        __syncthreads();
        ldK(nc);
        __syncthreads();

        float c[16][4];
#pragma unroll
        for (int nt = 0; nt < 16; nt++) { c[nt][0] = c[nt][1] = c[nt][2] = c[nt][3] = 0.0f; }
#pragma unroll
        for (int kt = 0; kt < 8; kt++) {
            const int lx = lane ^ kt;
#pragma unroll
            for (int nt = 0; nt < 16; nt++) {
                uint2 b = *(const uint2*)(Ks + ((kt * 16 + nt) * 32 + lx) * 2);
                mma8(c[nt], aq[kt], b.x, b.y);
            }
        }
        float* a0 = attnb + (long)(r0 + g) * Sc + nc * 128 + 2 * t;
        float* a1 = attnb + (long)(r0 + g + 8) * Sc + nc * 128 + 2 * t;
#pragma unroll
        for (int nt = 0; nt < 16; nt++) {
            *(float2*)(a0 + nt * 8) = make_float2(__expf(c[nt][0] * 0.125f) * inv0,
                                                  __expf(c[nt][1] * 0.125f) * inv0);
            *(float2*)(a1 + nt * 8) = make_float2(__expf(c[nt][2] * 0.125f) * inv1,
                                                  __expf(c[nt][3] * 0.125f) * inv1);
        }
    }

    // ---- ctx epilogue ----
    {
        const int b = z >> 4, h = z & 15;
        float* cp = ctx + (long)b * Sc * Ec + (long)(m0 + r0 + g) * Ec + h * Dc + 2 * t;
#pragma unroll
        for (int ntv = 0; ntv < 8; ntv++) {
            *(float2*)(cp + ntv * 8) =
                make_float2(ctxacc[ntv][0] * inv0, ctxacc[ntv][1] * inv0);
            *(float2*)(cp + 8 * Ec + ntv * 8) =
                make_float2(ctxacc[ntv][2] * inv1, ctxacc[ntv][3] * inv1);
        }
    }
}

// ---------------------------------------------------------------------------
extern "C" void kernel_launch(void* const* d_in, const int* in_sizes, int n_in,
                              void* d_out, int out_size)
{
    const float* query = (const float*)d_in[0];
    const float* key   = (const float*)d_in[1];
    const float* value = (const float*)d_in[2];
    const float* Wq    = (const float*)d_in[3];
    const float* bq    = (const float*)d_in[4];
    const float* Wk    = (const float*)d_in[5];
    const float* bk    = (const float*)d_in[6];
    const float* Wv    = (const float*)d_in[7];
    const float* bv    = (const float*)d_in[8];
    const float* Wo    = (const float*)d_in[9];
    const float* bo    = (const float*)d_in[10];

    float* out  = (float*)d_out;
    float* attn = out + (long)Bc * Sc * Ec;

    float *q, *k, *vT, *ctx;
    cudaGetSymbolAddress((void**)&q,   g_q);
    cudaGetSymbolAddress((void**)&k,   g_k);
    cudaGetSymbolAddress((void**)&vT,  g_vT);
    cudaGetSymbolAddress((void**)&ctx, g_ctx);

    constexpr int SMEM128 = (2 * 4096 + 2 * 128 * 32) * 4;  // 65536

    cudaFuncSetAttribute((const void*)qkv_gemm,         cudaFuncAttributeMaxDynamicSharedMemorySize, SMEM128);
    cudaFuncSetAttribute((const void*)mma_gemm<128, 0>, cudaFuncAttributeMaxDynamicSharedMemorySize, SMEM128);
    cudaFuncSetAttribute((const void*)attn2,            cudaFuncAttributeMaxDynamicSharedMemorySize, ATT2_SMEM);

    const dim3 blk(256);

    // 1) fused Q/K/V projections (one launch, z selects target)
    qkv_gemm<<<dim3(Ec / 128, (Bc * Sc) / 128, 3), blk, SMEM128>>>(
        query, key, value, Wq, Wk, Wv, bq, bk, bv, q, k, vT);

    // 2) attention: single attn write + ctx
    attn2<<<dim3(Sc / 128, Bc * Hc), blk, ATT2_SMEM>>>(q, k, vT, attn, ctx);

    // 3) out = ctx @ Wo^T + bo
    mma_gemm<128, 0><<<dim3(Ec / 128, (Bc * Sc) / 128, 1), blk, SMEM128>>>(
        ctx, Wo, bo, out, Ec, Ec, 0, 0, 0, 1.0f);
}

// round 7
// speedup vs baseline: 1.6779x; 1.0338x over previous
#include <cuda_runtime.h>
#include <cstdint>

static constexpr int Bc = 2;
static constexpr int Sc = 2048;
static constexpr int Ec = 1024;
static constexpr int Hc = 16;
static constexpr int Dc = 64;

// Scratch (__device__ globals per allocation rules)
__device__ float g_q  [(size_t)Bc * Hc * Sc * Dc];   // (b,h,s,d)   tf32-rounded
__device__ float g_k  [(size_t)Bc * Hc * Sc * Dc];   // (b,h,s,d)   tf32-rounded
__device__ float g_vT [(size_t)Bc * Hc * Dc * Sc];   // (b,h,d,s)   tf32-rounded
__device__ float g_ctx[(size_t)Bc * Sc * Ec];        // (b,s,E)

// tf32 round-to-nearest via single cvt instruction
__device__ __forceinline__ uint32_t tf32r(float x) {
    uint32_t r;
    asm("cvt.rna.tf32.f32 %0, %1;" : "=r"(r) : "f"(x));
    return r;
}
__device__ __forceinline__ float tf32f(float x) {
    return __uint_as_float(tf32r(x));
}

__device__ __forceinline__ void mma8(float* d, const uint32_t* a, uint32_t b0, uint32_t b1) {
    asm volatile(
        "mma.sync.aligned.m16n8k8.row.col.f32.tf32.tf32.f32 "
        "{%0,%1,%2,%3}, {%4,%5,%6,%7}, {%8,%9}, {%0,%1,%2,%3};"
        : "+f"(d[0]), "+f"(d[1]), "+f"(d[2]), "+f"(d[3])
        : "r"(a[0]), "r"(a[1]), "r"(a[2]), "r"(a[3]), "r"(b0), "r"(b1));
}

// ---------------------------------------------------------------------------
// Out-projection GEMM (row-major epilogue). C = A @ W^T + bias.
// ---------------------------------------------------------------------------
__global__ __launch_bounds__(256)
void mma_gemm_out(const float* __restrict__ A, const float* __restrict__ Bm,
                  const float* __restrict__ bias, float* __restrict__ C,
                  int N, int K)
{
    extern __shared__ uint32_t sm[];
    uint32_t* Abuf = sm;
    uint32_t* Bbuf = sm + 2 * 4096;

    const int tid  = threadIdx.x;
    const int wid  = tid >> 5;
    const int lane = tid & 31;
    const int wm   = wid & 1;
    const int wn   = wid >> 1;

    const int m0 = blockIdx.y * 128;
    const int n0 = blockIdx.x * 128;

    const int lrow  = tid >> 3;
    const int c4    = (tid & 7) * 4;
    const int kt_s  = c4 >> 3;
    const int reghi = (c4 >> 2) & 1;

    const float* Ap = A  + (long)m0 * K;
    const float* Bp = Bm + (long)n0 * K;

    float4 aR[4], bR[4];
    float acc[4][4][4];
#pragma unroll
    for (int i = 0; i < 4; i++)
#pragma unroll
        for (int j = 0; j < 4; j++)
#pragma unroll
            for (int r = 0; r < 4; r++) acc[i][j][r] = 0.0f;

    auto ldg = [&](int it) {
        const int k0 = it << 5;
#pragma unroll
        for (int i = 0; i < 4; i++) {
            aR[i] = *(const float4*)(Ap + (long)(lrow + i * 32) * K + k0 + c4);
            bR[i] = *(const float4*)(Bp + (long)(lrow + i * 32) * K + k0 + c4);
        }
    };

    auto sts = [&](int s) {
        uint32_t* Asd = Abuf + s * 4096;
        uint32_t* Bsd = Bbuf + s * 4096;
#pragma unroll
        for (int i = 0; i < 4; i++) {
            const int row = lrow + i * 32;
            const int mt  = row >> 4;
            const int reg = ((row >> 3) & 1) + 2 * reghi;
            const int lb  = (row & 7) * 4;
            const float* va = (const float*)&aR[i];
            const float* vb = (const float*)&bR[i];
            const int nt = row >> 3;
#pragma unroll
            for (int j = 0; j < 4; j++) {
                const int ln = (lb + j) ^ kt_s;
                Asd[((kt_s * 8 + mt) * 32 + ln) * 4 + reg]    = tf32r(va[j]);
                Bsd[((kt_s * 16 + nt) * 32 + ln) * 2 + reghi] = tf32r(vb[j]);
            }
        }
    };

    auto compute = [&](int s) {
        const uint32_t* Asd = Abuf + s * 4096;
        const uint32_t* Bsd = Bbuf + s * 4096;
#pragma unroll
        for (int kt = 0; kt < 4; kt++) {
            const int lx = lane ^ kt;
            uint32_t a[4][4], b[4][2];
#pragma unroll
            for (int mt = 0; mt < 4; mt++) {
                uint4 v = *(const uint4*)(Asd + ((kt * 8 + wm * 4 + mt) * 32 + lx) * 4);
                a[mt][0] = v.x; a[mt][1] = v.y; a[mt][2] = v.z; a[mt][3] = v.w;
            }
#pragma unroll
            for (int nt = 0; nt < 4; nt++) {
                uint2 v = *(const uint2*)(Bsd + ((kt * 16 + wn * 4 + nt) * 32 + lx) * 2);
                b[nt][0] = v.x; b[nt][1] = v.y;
            }
#pragma unroll
            for (int mt = 0; mt < 4; mt++)
#pragma unroll
                for (int nt = 0; nt < 4; nt++)
                    mma8(acc[mt][nt], a[mt], b[nt][0], b[nt][1]);
        }
    };

    const int nk = K >> 5;
    ldg(0);
    sts(0);
    __syncthreads();
    for (int it = 0; it < nk; it++) {
        const int s = it & 1;
        if (it + 1 < nk) ldg(it + 1);
        compute(s);
        if (it + 1 < nk) { sts(1 - s); __syncthreads(); }
    }

    const int g  = lane >> 2;
    const int t2 = (lane & 3) * 2;
#pragma unroll
    for (int mt = 0; mt < 4; mt++) {
#pragma unroll
        for (int nt = 0; nt < 4; nt++) {
            const int row = m0 + wm * 64 + mt * 16 + g;
            const int col = n0 + wn * 32 + nt * 8 + t2;
            const float b0 = bias[col], b1 = bias[col + 1];
            *(float2*)(C + (long)row * N + col) =
                make_float2(acc[mt][nt][0] + b0, acc[mt][nt][1] + b1);
            *(float2*)(C + (long)(row + 8) * N + col) =
                make_float2(acc[mt][nt][2] + b0, acc[mt][nt][3] + b1);
        }
    }
}

// ---------------------------------------------------------------------------
// Fused QKV projection: one launch, blockIdx.z selects {Q,K,V}.
// Q,K -> head-split (b,h,s,d); V -> transposed head-split (b,h,d,s).
// Outputs are tf32-PRE-ROUNDED so attn2 staging is pure data movement.
// ---------------------------------------------------------------------------
__global__ __launch_bounds__(256)
void qkv_gemm(const float* __restrict__ in0, const float* __restrict__ in1,
              const float* __restrict__ in2,
              const float* __restrict__ W0, const float* __restrict__ W1,
              const float* __restrict__ W2,
              const float* __restrict__ bi0, const float* __restrict__ bi1,
              const float* __restrict__ bi2,
              float* __restrict__ d0, float* __restrict__ d1, float* __restrict__ d2)
{
    constexpr int K = 1024;
    const float* A; const float* Bm; const float* bias; float* C;
    if (blockIdx.z == 0)      { A = in0; Bm = W0; bias = bi0; C = d0; }
    else if (blockIdx.z == 1) { A = in1; Bm = W1; bias = bi1; C = d1; }
    else                      { A = in2; Bm = W2; bias = bi2; C = d2; }

    extern __shared__ uint32_t sm[];
    uint32_t* Abuf = sm;
    uint32_t* Bbuf = sm + 2 * 4096;

    const int tid  = threadIdx.x;
    const int wid  = tid >> 5;
    const int lane = tid & 31;
    const int wm   = wid & 1;
    const int wn   = wid >> 1;

    const int m0 = blockIdx.y * 128;
    const int n0 = blockIdx.x * 128;

    const int lrow  = tid >> 3;
    const int c4    = (tid & 7) * 4;
    const int kt_s  = c4 >> 3;
    const int reghi = (c4 >> 2) & 1;

    const float* Ap = A  + (long)m0 * K;
    const float* Bp = Bm + (long)n0 * K;

    float4 aR[4], bR[4];
    float acc[4][4][4];
#pragma unroll
    for (int i = 0; i < 4; i++)
#pragma unroll
        for (int j = 0; j < 4; j++)
#pragma unroll
            for (int r = 0; r < 4; r++) acc[i][j][r] = 0.0f;

    auto ldg = [&](int it) {
        const int k0 = it << 5;
#pragma unroll
        for (int i = 0; i < 4; i++) {
            aR[i] = *(const float4*)(Ap + (long)(lrow + i * 32) * K + k0 + c4);
            bR[i] = *(const float4*)(Bp + (long)(lrow + i * 32) * K + k0 + c4);
        }
    };

    auto sts = [&](int s) {
        uint32_t* Asd = Abuf + s * 4096;
        uint32_t* Bsd = Bbuf + s * 4096;
#pragma unroll
        for (int i = 0; i < 4; i++) {
            const int row = lrow + i * 32;
            const int mt  = row >> 4;
            const int reg = ((row >> 3) & 1) + 2 * reghi;
            const int lb  = (row & 7) * 4;
            const float* va = (const float*)&aR[i];
            const float* vb = (const float*)&bR[i];
            const int nt = row >> 3;
#pragma unroll
            for (int j = 0; j < 4; j++) {
                const int ln = (lb + j) ^ kt_s;
                Asd[((kt_s * 8 + mt) * 32 + ln) * 4 + reg]    = tf32r(va[j]);
                Bsd[((kt_s * 16 + nt) * 32 + ln) * 2 + reghi] = tf32r(vb[j]);
            }
        }
    };

    auto compute = [&](int s) {
        const uint32_t* Asd = Abuf + s * 4096;
        const uint32_t* Bsd = Bbuf + s * 4096;
#pragma unroll
        for (int kt = 0; kt < 4; kt++) {
            const int lx = lane ^ kt;
            uint32_t a[4][4], b[4][2];
#pragma unroll
            for (int mt = 0; mt < 4; mt++) {
                uint4 v = *(const uint4*)(Asd + ((kt * 8 + wm * 4 + mt) * 32 + lx) * 4);
                a[mt][0] = v.x; a[mt][1] = v.y; a[mt][2] = v.z; a[mt][3] = v.w;
            }
#pragma unroll
            for (int nt = 0; nt < 4; nt++) {
                uint2 v = *(const uint2*)(Bsd + ((kt * 16 + wn * 4 + nt) * 32 + lx) * 2);
                b[nt][0] = v.x; b[nt][1] = v.y;
            }
#pragma unroll
            for (int mt = 0; mt < 4; mt++)
#pragma unroll
                for (int nt = 0; nt < 4; nt++)
                    mma8(acc[mt][nt], a[mt], b[nt][0], b[nt][1]);
        }
    };

    ldg(0);
    sts(0);
    __syncthreads();
    for (int it = 0; it < 32; it++) {
        const int s = it & 1;
        if (it + 1 < 32) ldg(it + 1);
        compute(s);
        if (it + 1 < 32) { sts(1 - s); __syncthreads(); }
    }

    const int g  = lane >> 2;
    const int t2 = (lane & 3) * 2;
    const bool transp = (blockIdx.z == 2);
#pragma unroll
    for (int mt = 0; mt < 4; mt++) {
#pragma unroll
        for (int nt = 0; nt < 4; nt++) {
            const int row = m0 + wm * 64 + mt * 16 + g;
            const int col = n0 + wn * 32 + nt * 8 + t2;
            const float b0 = bias[col], b1 = bias[col + 1];
            const float c0 = tf32f(acc[mt][nt][0] + b0);
            const float c1 = tf32f(acc[mt][nt][1] + b1);
            const float c2 = tf32f(acc[mt][nt][2] + b0);
            const float c3 = tf32f(acc[mt][nt][3] + b1);
            const int b = row >> 11, si = row & 2047, h = col >> 6, d = col & 63;
            if (!transp) {
                float* p = C + (((long)(b * Hc + h) * Sc + si) * Dc + d);
                *(float2*)p            = make_float2(c0, c1);
                *(float2*)(p + 8 * Dc) = make_float2(c2, c3);
            } else {
                float* p = C + (((long)(b * Hc + h) * Dc + d) * Sc + si);
                p[0] = c0;  p[Sc] = c1;
                p[8] = c2;  p[Sc + 8] = c3;
            }
        }
    }
}

// ---------------------------------------------------------------------------
// attn2: CTA = 128 q-rows x one head, 256 thr. Warp = 16 FULL rows.
// Pass 1: S-MMA -> exp -> reg rowsums + shuffle C->A frags -> AV-MMA (unnorm).
// ctx epilogue right after reduce (frees ctxacc regs for pass 2 pipeline).
// Pass 2: DOUBLE-BUFFERED recompute of S (Ks<->Vs), write normalized attn.
// Inputs are tf32-pre-rounded; staging is pure bit movement.
// ---------------------------------------------------------------------------
static constexpr int ATT2_SMEM = 3 * 8192 * 4;

__global__ __launch_bounds__(256, 2)
void attn2(const float* __restrict__ q, const float* __restrict__ k,
           const float* __restrict__ vT, float* __restrict__ attn,
           float* __restrict__ ctx)
{
    extern __shared__ uint32_t sm[];
    uint32_t* Qs = sm;            // 8192
    uint32_t* Ks = sm + 8192;     // 8192
    uint32_t* Vs = sm + 16384;    // 8192

    const int tid  = threadIdx.x;
    const int lane = tid & 31;
    const int wid  = tid >> 5;
    const int g    = lane >> 2;
    const int t    = lane & 3;
    const int z    = blockIdx.y;
    const int m0   = blockIdx.x * 128;

    const float* qb = q  + ((long)z * Sc + m0) * Dc;
    const float* kb = k  + (long)z * Sc * Dc;
    const float* vb = vT + (long)z * Dc * Sc;
    float* attnb    = attn + (long)z * Sc * Sc + (long)m0 * Sc;

    // ---- Q -> frag smem once (pure move, inputs pre-rounded), then to regs ----
#pragma unroll
    for (int i = 0; i < 8; i++) {
        const int idx = tid + i * 256;
        const int row = idx >> 4;
        const int c4  = (idx & 15) * 4;
        const int kt = c4 >> 3, reghi = (c4 >> 2) & 1;
        const int mt = row >> 4, reg = ((row >> 3) & 1) + 2 * reghi;
        const int ln0 = (row & 7) * 4;
        float4 v = *(const float4*)(qb + (long)row * Dc + c4);
        const float* pv = (const float*)&v;
#pragma unroll
        for (int j = 0; j < 4; j++) {
            const int ln = (ln0 + j) ^ kt;
            Qs[((kt * 8 + mt) * 32 + ln) * 4 + reg] = __float_as_uint(pv[j]);
        }
    }
    __syncthreads();
    uint32_t aq[8][4];
#pragma unroll
    for (int kt = 0; kt < 8; kt++) {
        uint4 v = *(const uint4*)(Qs + ((kt * 8 + wid) * 32 + (lane ^ kt)) * 4);
        aq[kt][0] = v.x; aq[kt][1] = v.y; aq[kt][2] = v.z; aq[kt][3] = v.w;
    }

    auto ldK = [&](int nc) {
#pragma unroll
        for (int i = 0; i < 8; i++) {
            const int idx = tid + i * 256;
            const int n  = idx >> 4;
            const int c4 = (idx & 15) * 4;
            const int kt = c4 >> 3, reghi = (c4 >> 2) & 1;
            const int nt = n >> 3;
            const int ln0 = (n & 7) * 4;
            float4 v = *(const float4*)(kb + (long)(nc * 128 + n) * Dc + c4);
            const float* pv = (const float*)&v;
#pragma unroll
            for (int j = 0; j < 4; j++) {
                const int ln = (ln0 + j) ^ kt;
                Ks[((kt * 16 + nt) * 32 + ln) * 2 + reghi] = __float_as_uint(pv[j]);
            }
        }
    };
    auto ldV = [&](int nc) {
#pragma unroll
        for (int i = 0; i < 8; i++) {
            const int idx = tid + i * 256;
            const int d  = idx >> 5;
            const int c4 = (idx & 31) * 4;
            const int kt2 = c4 >> 3, s2 = kt2 & 7, reghi = (c4 >> 2) & 1;
            const int nt = d >> 3;
            const int ln0 = (d & 7) * 4;
            float4 v = *(const float4*)(vb + (long)d * Sc + nc * 128 + c4);
            const float* pv = (const float*)&v;
#pragma unroll
            for (int j = 0; j < 4; j++) {
                const int ln = (ln0 + j) ^ s2;
                Vs[((kt2 * 8 + nt) * 32 + ln) * 2 + reghi] = __float_as_uint(pv[j]);
            }
        }
    };

    float ctxacc[8][4];
#pragma unroll
    for (int i = 0; i < 8; i++)
#pragma unroll
        for (int r = 0; r < 4; r++) ctxacc[i][r] = 0.0f;
    float rs0 = 0.0f, rs1 = 0.0f;

    const int lsrc0 = (lane & ~3) | (t >> 1);
    const int lsrc1 = lsrc0 + 2;
    const bool odd  = (t & 1);

    // ================= pass 1 =================
#pragma unroll 1
    for (int nc = 0; nc < 16; nc++) {
        __syncthreads();
        ldK(nc);
        ldV(nc);
        __syncthreads();

        float c[16][4];
#pragma unroll
        for (int nt = 0; nt < 16; nt++) { c[nt][0] = c[nt][1] = c[nt][2] = c[nt][3] = 0.0f; }
#pragma unroll
        for (int kt = 0; kt < 8; kt++) {
            const int lx = lane ^ kt;
#pragma unroll
            for (int nt = 0; nt < 16; nt++) {
                uint2 b = *(const uint2*)(Ks + ((kt * 16 + nt) * 32 + lx) * 2);
                mma8(c[nt], aq[kt], b.x, b.y);
            }
        }
#pragma unroll
        for (int nt = 0; nt < 16; nt++) {
            c[nt][0] = __expf(c[nt][0] * 0.125f);
            c[nt][1] = __expf(c[nt][1] * 0.125f);
            c[nt][2] = __expf(c[nt][2] * 0.125f);
            c[nt][3] = __expf(c[nt][3] * 0.125f);
            rs0 += c[nt][0] + c[nt][1];
            rs1 += c[nt][2] + c[nt][3];
        }
        // AV: shuffle C-frags into A-frags, MMA against V
#pragma unroll
        for (int kt2 = 0; kt2 < 16; kt2++) {
            const float x0 = __shfl_sync(0xFFFFFFFFu, c[kt2][0], lsrc0);
            const float x1 = __shfl_sync(0xFFFFFFFFu, c[kt2][1], lsrc0);
            const float y0 = __shfl_sync(0xFFFFFFFFu, c[kt2][2], lsrc0);
            const float y1 = __shfl_sync(0xFFFFFFFFu, c[kt2][3], lsrc0);
            const float u0 = __shfl_sync(0xFFFFFFFFu, c[kt2][0], lsrc1);
            const float u1 = __shfl_sync(0xFFFFFFFFu, c[kt2][1], lsrc1);
            const float w0 = __shfl_sync(0xFFFFFFFFu, c[kt2][2], lsrc1);
            const float w1 = __shfl_sync(0xFFFFFFFFu, c[kt2][3], lsrc1);
            uint32_t pa[4];
            pa[0] = tf32r(odd ? x1 : x0);
            pa[1] = tf32r(odd ? y1 : y0);
            pa[2] = tf32r(odd ? u1 : u0);
            pa[3] = tf32r(odd ? w1 : w0);
            const int lx2 = lane ^ (kt2 & 7);
#pragma unroll
            for (int ntv = 0; ntv < 8; ntv++) {
                uint2 b = *(const uint2*)(Vs + ((kt2 * 8 + ntv) * 32 + lx2) * 2);
                mma8(ctxacc[ntv], pa, b.x, b.y);
            }
        }
    }

    // row inverses (rows are warp-exclusive; reduce within quad)
    rs0 += __shfl_xor_sync(0xFFFFFFFFu, rs0, 1);
    rs0 += __shfl_xor_sync(0xFFFFFFFFu, rs0, 2);
    rs1 += __shfl_xor_sync(0xFFFFFFFFu, rs1, 1);
    rs1 += __shfl_xor_sync(0xFFFFFFFFu, rs1, 2);
    const float inv0 = 1.0f / rs0;
    const float inv1 = 1.0f / rs1;
    const int r0 = wid * 16;

    // ---- ctx epilogue NOW (frees ctxacc for pass-2 pipeline regs) ----
    {
        const int b = z >> 4, h = z & 15;
        float* cp = ctx + (long)b * Sc * Ec + (long)(m0 + r0 + g) * Ec + h * Dc + 2 * t;
#pragma unroll
        for (int ntv = 0; ntv < 8; ntv++) {
            *(float2*)(cp + ntv * 8) =
                make_float2(ctxacc[ntv][0] * inv0, ctxacc[ntv][1] * inv0);
            *(float2*)(cp + 8 * Ec + ntv * 8) =
                make_float2(ctxacc[ntv][2] * inv1, ctxacc[ntv][3] * inv1);
        }
    }

    // ================= pass 2: double-buffered recompute, write attn ========
    float4 kreg[8];
    auto ldgK2 = [&](int nc) {
#pragma unroll
        for (int i = 0; i < 8; i++) {
            const int idx = tid + i * 256;
            const int n  = idx >> 4;
            const int c4 = (idx & 15) * 4;
            kreg[i] = *(const float4*)(kb + (long)(nc * 128 + n) * Dc + c4);
        }
    };
    auto stsK2 = [&](uint32_t* buf) {
#pragma unroll
        for (int i = 0; i < 8; i++) {
            const int idx = tid + i * 256;
            const int n  = idx >> 4;
            const int c4 = (idx & 15) * 4;
            const int kt = c4 >> 3, reghi = (c4 >> 2) & 1;
            const int nt = n >> 3;
            const int ln0 = (n & 7) * 4;
            const float* pv = (const float*)&kreg[i];
#pragma unroll
            for (int j = 0; j < 4; j++) {
                const int ln = (ln0 + j) ^ kt;
                buf[((kt * 16 + nt) * 32 + ln) * 2 + reghi] = __float_as_uint(pv[j]);
            }
        }
    };

    __syncthreads();                  // pass-1 readers of Ks/Vs done
    ldgK2(0);
    stsK2(Ks);
    __syncthreads();

#pragma unroll 1
    for (int nc = 0; nc < 16; nc++) {
        if (nc + 1 < 16) ldgK2(nc + 1);

        const uint32_t* buf = (nc & 1) ? Vs : Ks;
        float c[16][4];
#pragma unroll
        for (int nt = 0; nt < 16; nt++) { c[nt][0] = c[nt][1] = c[nt][2] = c[nt][3] = 0.0f; }
#pragma unroll
        for (int kt = 0; kt < 8; kt++) {
            const int lx = lane ^ kt;
#pragma unroll
            for (int nt = 0; nt < 16; nt++) {
                uint2 b = *(const uint2*)(buf + ((kt * 16 + nt) * 32 + lx) * 2);
                mma8(c[nt], aq[kt], b.x, b.y);
            }
        }
        float* a0 = attnb + (long)(r0 + g) * Sc + nc * 128 + 2 * t;
        float* a1 = attnb + (long)(r0 + g + 8) * Sc + nc * 128 + 2 * t;
#pragma unroll
        for (int nt = 0; nt < 16; nt++) {
            *(float2*)(a0 + nt * 8) = make_float2(__expf(c[nt][0] * 0.125f) * inv0,
                                                  __expf(c[nt][1] * 0.125f) * inv0);
            *(float2*)(a1 + nt * 8) = make_float2(__expf(c[nt][2] * 0.125f) * inv1,
                                                  __expf(c[nt][3] * 0.125f) * inv1);
        }

        if (nc + 1 < 16) stsK2(((nc + 1) & 1) ? Vs : Ks);
        __syncthreads();
    }
}

// ---------------------------------------------------------------------------
extern "C" void kernel_launch(void* const* d_in, const int* in_sizes, int n_in,
                              void* d_out, int out_size)
{
    const float* query = (const float*)d_in[0];
    const float* key   = (const float*)d_in[1];
    const float* value = (const float*)d_in[2];
    const float* Wq    = (const float*)d_in[3];
    const float* bq    = (const float*)d_in[4];
    const float* Wk    = (const float*)d_in[5];
    const float* bk    = (const float*)d_in[6];
    const float* Wv    = (const float*)d_in[7];
    const float* bv    = (const float*)d_in[8];
    const float* Wo    = (const float*)d_in[9];
    const float* bo    = (const float*)d_in[10];

    float* out  = (float*)d_out;
    float* attn = out + (long)Bc * Sc * Ec;

    float *q, *k, *vT, *ctx;
    cudaGetSymbolAddress((void**)&q,   g_q);
    cudaGetSymbolAddress((void**)&k,   g_k);
    cudaGetSymbolAddress((void**)&vT,  g_vT);
    cudaGetSymbolAddress((void**)&ctx, g_ctx);

    constexpr int SMEM128 = (2 * 4096 + 2 * 4096) * 4;  // 65536

    cudaFuncSetAttribute((const void*)qkv_gemm,     cudaFuncAttributeMaxDynamicSharedMemorySize, SMEM128);
    cudaFuncSetAttribute((const void*)mma_gemm_out, cudaFuncAttributeMaxDynamicSharedMemorySize, SMEM128);
    cudaFuncSetAttribute((const void*)attn2,        cudaFuncAttributeMaxDynamicSharedMemorySize, ATT2_SMEM);

    const dim3 blk(256);

    // 1) fused Q/K/V projections (pre-rounded tf32 outputs)
    qkv_gemm<<<dim3(Ec / 128, (Bc * Sc) / 128, 3), blk, SMEM128>>>(
        query, key, value, Wq, Wk, Wv, bq, bk, bv, q, k, vT);

    // 2) attention: single attn write + ctx
    attn2<<<dim3(Sc / 128, Bc * Hc), blk, ATT2_SMEM>>>(q, k, vT, attn, ctx);

    // 3) out = ctx @ Wo^T + bo
    mma_gemm_out<<<dim3(Ec / 128, (Bc * Sc) / 128, 1), blk, SMEM128>>>(
        ctx, Wo, bo, out, Ec, Ec);
}